// round 7
// baseline (speedup 1.0000x reference)
#include <cuda_runtime.h>
#include <cuda_fp16.h>
#include <math.h>

#define BB 32
#define II 1024
#define CC 128
#define JJ 32
#define DD 64
#define JD 2048            // JJ*DD
#define IBLK 8             // i's per GEMM block
#define GCH (II/IBLK)      // 128 GEMM chunks
#define RCH 64             // route chunks
#define RICH (II/RCH)      // 16 i's per route block

// Scratch (device globals: no allocation in kernel_launch)
__device__ float g_uhat[(size_t)BB * II * JD];   // [b][i][j*64+d], 256 MiB
__device__ float g_spart[GCH][BB * JD];          // partial s sums, 32 MiB
__device__ float g_b1[(size_t)BB * II * JJ];     // routing logits after agree1
__device__ float g_v[BB * JD];                   // current v[b][j][d]

// ---------------------------------------------------------------------------
// fp16 mma helper (m16n8k16, fp32 accumulate)
// ---------------------------------------------------------------------------
__device__ __forceinline__ void mma_f16(float c[4],
                                        unsigned a0, unsigned a1, unsigned a2, unsigned a3,
                                        unsigned b0, unsigned b1) {
    asm volatile(
        "mma.sync.aligned.m16n8k16.row.col.f32.f16.f16.f32 "
        "{%0,%1,%2,%3}, {%4,%5,%6,%7}, {%8,%9}, {%0,%1,%2,%3};"
        : "+f"(c[0]), "+f"(c[1]), "+f"(c[2]), "+f"(c[3])
        : "r"(a0), "r"(a1), "r"(a2), "r"(a3), "r"(b0), "r"(b1));
}

__device__ __forceinline__ unsigned h2u(__half2 h) {
    return *reinterpret_cast<unsigned*>(&h);
}

// split float2 into fp16 hi + fp16 lo (Markidis), packed half2
__device__ __forceinline__ void split2(float2 w, unsigned& hi, unsigned& lo) {
    __half2 h = __floats2half2_rn(w.x, w.y);
    float2 r = make_float2(w.x - __low2float(h), w.y - __high2float(h));
    __half2 l = __floats2half2_rn(r.x, r.y);
    hi = h2u(h); lo = h2u(l);
}

// ---------------------------------------------------------------------------
// Kernel 1: u_hat GEMM, fp16x3 compensated, FUSED with route-1 i-reduction.
// Block = (jt: 128-wide jd tile, chunk: 8 consecutive i). Loops the 8 i's,
// writes u_hat per i, accumulates s-partials in registers, writes g_spart
// once at the end. W streamed read-once with depth-2 prefetch carried
// across i boundaries.
// ---------------------------------------------------------------------------
#define XS 136   // half-stride per row: conflict-free half2 fragment reads

__global__ void __launch_bounds__(256, 2)
gemm_kernel(const float* __restrict__ x, const float* __restrict__ W) {
    __shared__ __half xh[32 * XS];
    __shared__ __half xl[32 * XS];

    const int jt   = blockIdx.x;          // 0..15 -> jd base = jt*128
    const int i0   = blockIdx.y * IBLK;
    const int tid  = threadIdx.x;
    const int lane = tid & 31;
    const int warp = tid >> 5;

    const int nbase = jt * 128 + warp * 16;   // warp's jd base (16 wide)
    const float2* Pq[2];
#pragma unroll
    for (int q = 0; q < 2; q++) {
        int n = nbase + q * 8 + (lane >> 2);
        int j = n >> 6, d = n & 63;
        Pq[q] = (const float2*)(W + ((size_t)j * II * DD + d) * CC) + (lane & 3);
    }

    const int arow = lane >> 2;
    const int acol = lane & 3;

    float sacc[2][2][4] = {};
    float2 bf[2][2][2];   // [buf parity][q][half]

    // prefetch global steps 0,1 (i = i0, s = 0,1)
#pragma unroll
    for (int g = 0; g < 2; g++) {
        size_t o = ((size_t)i0 + (g >> 3)) * 4096 + (g & 7) * 8;
#pragma unroll
        for (int q = 0; q < 2; q++) {
            bf[g & 1][q][0] = Pq[q][o];
            bf[g & 1][q][1] = Pq[q][o + 4];
        }
    }

    for (int t = 0; t < IBLK; t++) {
        const int i = i0 + t;
        // stage x[:, i, :] split into fp16 hi/lo, row-major [b][c]
        if (t) __syncthreads();           // protect smem from prev-iter readers
        for (int e = tid * 4; e < BB * CC; e += 1024) {
            int b = e >> 7, c = e & 127;
            float4 v = *(const float4*)(x + ((size_t)b * II + i) * CC + c);
            float f[4] = {v.x, v.y, v.z, v.w};
#pragma unroll
            for (int k = 0; k < 4; k++) {
                __half h = __float2half_rn(f[k]);
                xh[b * XS + c + k] = h;
                xl[b * XS + c + k] = __float2half_rn(f[k] - __half2float(h));
            }
        }
        __syncthreads();

        float acc[2][2][4] = {};

#pragma unroll
        for (int s = 0; s < 8; s++) {
            const int g = t * 8 + s;
            // consume buffer g&1: split B into hi/lo
            unsigned bh[2][2], bl[2][2];
#pragma unroll
            for (int q = 0; q < 2; q++) {
                split2(bf[g & 1][q][0], bh[q][0], bl[q][0]);
                split2(bf[g & 1][q][1], bh[q][1], bl[q][1]);
            }
            // prefetch global step g+2 into the freed buffer
            if (g + 2 < IBLK * 8) {
                size_t o = ((size_t)i0 + ((g + 2) >> 3)) * 4096 + ((g + 2) & 7) * 8;
#pragma unroll
                for (int q = 0; q < 2; q++) {
                    bf[g & 1][q][0] = Pq[q][o];
                    bf[g & 1][q][1] = Pq[q][o + 4];
                }
            }
            // A fragments (hi and lo), half2-packed
            unsigned ah[2][4], al[2][4];
#pragma unroll
            for (int mt = 0; mt < 2; mt++) {
                const int base = (mt * 16 + arow) * XS + s * 16 + acol * 2;
                ah[mt][0] = h2u(*(const __half2*)(xh + base));
                ah[mt][1] = h2u(*(const __half2*)(xh + base + 8 * XS));
                ah[mt][2] = h2u(*(const __half2*)(xh + base + 8));
                ah[mt][3] = h2u(*(const __half2*)(xh + base + 8 * XS + 8));
                al[mt][0] = h2u(*(const __half2*)(xl + base));
                al[mt][1] = h2u(*(const __half2*)(xl + base + 8 * XS));
                al[mt][2] = h2u(*(const __half2*)(xl + base + 8));
                al[mt][3] = h2u(*(const __half2*)(xl + base + 8 * XS + 8));
            }
#pragma unroll
            for (int q = 0; q < 2; q++)
#pragma unroll
                for (int mt = 0; mt < 2; mt++) {
                    mma_f16(acc[mt][q], ah[mt][0], ah[mt][1], ah[mt][2], ah[mt][3],
                            bl[q][0], bl[q][1]);
                    mma_f16(acc[mt][q], al[mt][0], al[mt][1], al[mt][2], al[mt][3],
                            bh[q][0], bh[q][1]);
                    mma_f16(acc[mt][q], ah[mt][0], ah[mt][1], ah[mt][2], ah[mt][3],
                            bh[q][0], bh[q][1]);
                }
        }

        // epilogue: store u_hat, accumulate s-partials in registers
#pragma unroll
        for (int mt = 0; mt < 2; mt++) {
            int b0r = mt * 16 + (lane >> 2);
#pragma unroll
            for (int q = 0; q < 2; q++) {
                int col = nbase + q * 8 + 2 * (lane & 3);
                *(float2*)(g_uhat + ((size_t)b0r * II + i) * JD + col) =
                    make_float2(acc[mt][q][0], acc[mt][q][1]);
                *(float2*)(g_uhat + ((size_t)(b0r + 8) * II + i) * JD + col) =
                    make_float2(acc[mt][q][2], acc[mt][q][3]);
#pragma unroll
                for (int k = 0; k < 4; k++) sacc[mt][q][k] += acc[mt][q][k];
            }
        }
    }

    // write s-partials for this (chunk): same fragment layout as u_hat
#pragma unroll
    for (int mt = 0; mt < 2; mt++) {
        int b0r = mt * 16 + (lane >> 2);
#pragma unroll
        for (int q = 0; q < 2; q++) {
            int col = nbase + q * 8 + 2 * (lane & 3);
            *(float2*)(&g_spart[blockIdx.y][b0r * JD + col]) =
                make_float2(sacc[mt][q][0], sacc[mt][q][1]);
            *(float2*)(&g_spart[blockIdx.y][(b0r + 8) * JD + col]) =
                make_float2(sacc[mt][q][2], sacc[mt][q][3]);
        }
    }
}

// ---------------------------------------------------------------------------
// Kernel 3: reduce partials + squash.  out==nullptr -> write g_v.
// ---------------------------------------------------------------------------
__global__ void squash_kernel(float scale, float* out, int nchunk) {
    int bj = blockIdx.x;
    int d  = threadIdx.x;
    float s = 0.f;
#pragma unroll 8
    for (int ch = 0; ch < nchunk; ch++) s += g_spart[ch][bj * 64 + d];
    s *= scale;

    float n2 = s * s;
#pragma unroll
    for (int off = 16; off; off >>= 1) n2 += __shfl_xor_sync(0xffffffffu, n2, off);
    __shared__ float tmp[2];
    if ((threadIdx.x & 31) == 0) tmp[threadIdx.x >> 5] = n2;
    __syncthreads();
    n2 = tmp[0] + tmp[1];

    float norm = sqrtf(n2);
    float f    = norm / (1.f + n2);
    float* dst = out ? out : g_v;
    dst[bj * 64 + d] = s * f;
}

// ---------------------------------------------------------------------------
// Kernel 4: fused agree + next-route partial-sum, register-resident,
// 2-way i-unroll, ONE dual softmax chain per pair: lanes 0-15 reduce i0's
// 32 logits (2 per lane), lanes 16-31 reduce i1's, via 4-shuffle butterflies
// within 16-lane halves. One __syncthreads per pair, 4-slot logit ring.
// Thread t owns (j = t>>3, d = (t&7)*8 .. +7).
// ---------------------------------------------------------------------------
template <bool FIRST>
__global__ void __launch_bounds__(256)
route_kernel() {
    __shared__ float bj_s[4][JJ];

    const int b    = blockIdx.x;
    const int ch   = blockIdx.y;
    const int tid  = threadIdx.x;
    const int lane = tid & 31;
    const int j    = tid >> 3;        // 0..31
    const int d0   = (tid & 7) * 8;
    const int hl   = lane & 15;       // position within 16-lane half

    float v[8];
#pragma unroll
    for (int k = 0; k < 8; k++) v[k] = g_v[b * JD + j * 64 + d0 + k];

    const float* ub = g_uhat + ((size_t)b * II + ch * RICH) * JD + j * 64 + d0;
    const float* bb = g_b1 + ((size_t)b * II + ch * RICH) * JJ + j;
    float* bw       = g_b1 + ((size_t)b * II + ch * RICH) * JJ + j;

    float sacc[8] = {};
    float u[2][8];
    float b1v[2];

    // prologue: load t = 0, 1
#pragma unroll
    for (int r = 0; r < 2; r++) {
        float4 a = *(const float4*)(ub + (size_t)r * JD);
        float4 c = *(const float4*)(ub + (size_t)r * JD + 4);
        u[r][0]=a.x; u[r][1]=a.y; u[r][2]=a.z; u[r][3]=a.w;
        u[r][4]=c.x; u[r][5]=c.y; u[r][6]=c.z; u[r][7]=c.w;
        b1v[r] = FIRST ? 0.f : bb[(size_t)r * JJ];
    }

#pragma unroll
    for (int p = 0; p < RICH / 2; p++) {
        // agreement dots for both i's of this pair
#pragma unroll
        for (int r = 0; r < 2; r++) {
            const int t = 2 * p + r;
            float dot = 0.f;
#pragma unroll
            for (int k = 0; k < 8; k++) dot = fmaf(u[r][k], v[k], dot);
            dot += __shfl_xor_sync(0xffffffffu, dot, 1);
            dot += __shfl_xor_sync(0xffffffffu, dot, 2);
            dot += __shfl_xor_sync(0xffffffffu, dot, 4);
            if ((lane & 7) == 0) {
                if (FIRST) bw[(size_t)t * JJ] = dot;   // b starts at 0
                bj_s[t & 3][j] = dot + b1v[r];
            }
        }
        __syncthreads();

        // prefetch next pair (overlaps the softmax chain below)
        float un[2][8];
        float b1n[2];
        if (p + 1 < RICH / 2) {
#pragma unroll
            for (int r = 0; r < 2; r++) {
                const size_t t = 2 * p + 2 + r;
                float4 a = *(const float4*)(ub + t * JD);
                float4 c = *(const float4*)(ub + t * JD + 4);
                un[r][0]=a.x; un[r][1]=a.y; un[r][2]=a.z; un[r][3]=a.w;
                un[r][4]=c.x; un[r][5]=c.y; un[r][6]=c.z; un[r][7]=c.w;
                b1n[r] = FIRST ? 0.f : bb[t * JJ];
            }
        }

        // dual softmax: half 0 (lanes 0-15) does i=2p, half 1 does i=2p+1
        {
            const int half = lane >> 4;
            const int slot = (2 * p + half) & 3;
            float x0 = bj_s[slot][hl];
            float x1 = bj_s[slot][hl + 16];
            float m = fmaxf(x0, x1);
#pragma unroll
            for (int off = 8; off; off >>= 1)
                m = fmaxf(m, __shfl_xor_sync(0xffffffffu, m, off));
            float e0 = __expf(x0 - m);
            float e1 = __expf(x1 - m);
            float ss = e0 + e1;
#pragma unroll
            for (int off = 8; off; off >>= 1)
                ss += __shfl_xor_sync(0xffffffffu, ss, off);
            float inv = __frcp_rn(ss);
            float r0 = e0 * inv;     // c for j = hl      (this half's i)
            float r1 = e1 * inv;     // c for j = hl + 16 (this half's i)

            // broadcast: c for (i0, j) lives in lane (j&15); (i1, j) in 16+(j&15)
            int js = j & 15;
            float a0 = __shfl_sync(0xffffffffu, r0, js);
            float a1 = __shfl_sync(0xffffffffu, r1, js);
            float c0 = (j < 16) ? a0 : a1;
            float b0 = __shfl_sync(0xffffffffu, r0, 16 + js);
            float b1x = __shfl_sync(0xffffffffu, r1, 16 + js);
            float c1 = (j < 16) ? b0 : b1x;

#pragma unroll
            for (int k = 0; k < 8; k++) sacc[k] = fmaf(c0, u[0][k], sacc[k]);
#pragma unroll
            for (int k = 0; k < 8; k++) sacc[k] = fmaf(c1, u[1][k], sacc[k]);
        }

        if (p + 1 < RICH / 2) {
#pragma unroll
            for (int r = 0; r < 2; r++) {
#pragma unroll
                for (int k = 0; k < 8; k++) u[r][k] = un[r][k];
                b1v[r] = b1n[r];
            }
        }
    }

    float* sp = &g_spart[ch][b * JD + tid * 8];
    *(float4*)(sp)     = make_float4(sacc[0], sacc[1], sacc[2], sacc[3]);
    *(float4*)(sp + 4) = make_float4(sacc[4], sacc[5], sacc[6], sacc[7]);
}

// ---------------------------------------------------------------------------
extern "C" void kernel_launch(void* const* d_in, const int* in_sizes, int n_in,
                              void* d_out, int out_size) {
    const float *x, *W;
    if (in_sizes[0] == BB * II * CC) { x = (const float*)d_in[0]; W = (const float*)d_in[1]; }
    else                             { x = (const float*)d_in[1]; W = (const float*)d_in[0]; }
    float* out = (float*)d_out;

    // 1) u_hat GEMM fused with s1 partial reduction
    gemm_kernel<<<dim3(16, GCH), 256>>>(x, W);
    // 2) v1 = squash(s1 / J)
    squash_kernel<<<BB * JJ, 64>>>(1.0f / (float)JJ, nullptr, GCH);
    // 3) agree1 + route2 partials; v2 = squash(s2)
    route_kernel<true><<<dim3(BB, RCH), 256>>>();
    squash_kernel<<<BB * JJ, 64>>>(1.0f, nullptr, RCH);
    // 4) agree2 + route3 partials; output = squash(s3)
    route_kernel<false><<<dim3(BB, RCH), 256>>>();
    squash_kernel<<<BB * JJ, 64>>>(1.0f, out, RCH);
}

// round 8
// speedup vs baseline: 1.1449x; 1.1449x over previous
#include <cuda_runtime.h>
#include <cuda_fp16.h>
#include <math.h>

#define BB 32
#define II 1024
#define CC 128
#define JJ 32
#define DD 64
#define JD 2048            // JJ*DD
#define NCH_R 32           // reduce chunks (init route)
#define ICH_R (II/NCH_R)   // 32 i's per reduce block
#define RCH 64             // route chunks
#define RICH (II/RCH)      // 16 i's per route block

// Scratch (device globals: no allocation in kernel_launch)
__device__ float g_uhat[(size_t)BB * II * JD];   // [b][i][j*64+d], 256 MiB
__device__ float g_spart[RCH][BB * JD];          // partial s sums, 16 MiB
__device__ float g_b1[(size_t)BB * II * JJ];     // routing logits after agree1
__device__ float g_v[BB * JD];                   // current v[b][j][d]

// tiny no-op kernels: shift the real GEMM to ncu's captured launch slot (idx 3)
__global__ void noop_kernel() {}

// ---------------------------------------------------------------------------
// fp16 mma helper (m16n8k16, fp32 accumulate)
// ---------------------------------------------------------------------------
__device__ __forceinline__ void mma_f16(float c[4],
                                        unsigned a0, unsigned a1, unsigned a2, unsigned a3,
                                        unsigned b0, unsigned b1) {
    asm volatile(
        "mma.sync.aligned.m16n8k16.row.col.f32.f16.f16.f32 "
        "{%0,%1,%2,%3}, {%4,%5,%6,%7}, {%8,%9}, {%0,%1,%2,%3};"
        : "+f"(c[0]), "+f"(c[1]), "+f"(c[2]), "+f"(c[3])
        : "r"(a0), "r"(a1), "r"(a2), "r"(a3), "r"(b0), "r"(b1));
}

__device__ __forceinline__ unsigned h2u(__half2 h) {
    return *reinterpret_cast<unsigned*>(&h);
}

// split float2 into fp16 hi + fp16 lo (Markidis), packed half2
__device__ __forceinline__ void split2(float2 w, unsigned& hi, unsigned& lo) {
    __half2 h = __floats2half2_rn(w.x, w.y);
    float2 r = make_float2(w.x - __low2float(h), w.y - __high2float(h));
    __half2 l = __floats2half2_rn(r.x, r.y);
    hi = h2u(h); lo = h2u(l);
}

// ---------------------------------------------------------------------------
// Kernel 1: u_hat GEMM, fp16x3 error-compensated (~fp32 accuracy).
// Per block: one i, 256-wide jd tile, all 32 b (M=32, N=256, K=128).
// A (x slice) staged in smem split hi/lo fp16; B (W) streamed from global
// as float2 (read exactly once), split hi/lo in registers, depth-1 prefetch.
// (round-6 structure, verbatim — the known-fastest GEMM so far)
// ---------------------------------------------------------------------------
#define XS 136   // half-stride per row: conflict-free half2 fragment reads

__global__ void __launch_bounds__(256, 2)
gemm_kernel(const float* __restrict__ x, const float* __restrict__ W) {
    __shared__ __half xh[32 * XS];
    __shared__ __half xl[32 * XS];

    const int i    = blockIdx.y;
    const int jt   = blockIdx.x;          // 0..7 -> jd base = jt*256
    const int tid  = threadIdx.x;
    const int lane = tid & 31;
    const int warp = tid >> 5;

    // Stage x[:, i, :] split into fp16 hi/lo, row-major [b][c]
    for (int e = tid * 4; e < BB * CC; e += 1024) {
        int b = e >> 7, c = e & 127;
        float4 v = *(const float4*)(x + ((size_t)b * II + i) * CC + c);
        float f[4] = {v.x, v.y, v.z, v.w};
#pragma unroll
        for (int k = 0; k < 4; k++) {
            __half h = __float2half_rn(f[k]);
            xh[b * XS + c + k] = h;
            xl[b * XS + c + k] = __float2half_rn(f[k] - __half2float(h));
        }
    }
    __syncthreads();

    const int nbase = jt * 256 + warp * 32;   // this warp's jd base (32 wide)
    const float2* Wp[4];
#pragma unroll
    for (int q = 0; q < 4; q++) {
        int n = nbase + q * 8 + (lane >> 2);
        int j = n >> 6, d = n & 63;
        Wp[q] = (const float2*)(W + (((size_t)j * II + i) * DD + d) * CC) + (lane & 3);
    }

    float acc[2][4][4] = {};
    float2 bf[2][4][2];
#pragma unroll
    for (int q = 0; q < 4; q++) { bf[0][q][0] = Wp[q][0]; bf[0][q][1] = Wp[q][4]; }

    const int arow = lane >> 2;
    const int acol = lane & 3;

#pragma unroll
    for (int s = 0; s < 8; s++) {          // K = 8 steps of 16
        const int cur = s & 1, nxt = cur ^ 1;
        if (s < 7) {
#pragma unroll
            for (int q = 0; q < 4; q++) {
                bf[nxt][q][0] = Wp[q][8 * (s + 1)];
                bf[nxt][q][1] = Wp[q][8 * (s + 1) + 4];
            }
        }
        unsigned ah[2][4], al[2][4];
#pragma unroll
        for (int mt = 0; mt < 2; mt++) {
            const int base = (mt * 16 + arow) * XS + s * 16 + acol * 2;
            ah[mt][0] = h2u(*(const __half2*)(xh + base));
            ah[mt][1] = h2u(*(const __half2*)(xh + base + 8 * XS));
            ah[mt][2] = h2u(*(const __half2*)(xh + base + 8));
            ah[mt][3] = h2u(*(const __half2*)(xh + base + 8 * XS + 8));
            al[mt][0] = h2u(*(const __half2*)(xl + base));
            al[mt][1] = h2u(*(const __half2*)(xl + base + 8 * XS));
            al[mt][2] = h2u(*(const __half2*)(xl + base + 8));
            al[mt][3] = h2u(*(const __half2*)(xl + base + 8 * XS + 8));
        }
#pragma unroll
        for (int q = 0; q < 4; q++) {
            unsigned bh0, bl0, bh1, bl1;
            split2(bf[cur][q][0], bh0, bl0);
            split2(bf[cur][q][1], bh1, bl1);
#pragma unroll
            for (int mt = 0; mt < 2; mt++) {
                mma_f16(acc[mt][q], ah[mt][0], ah[mt][1], ah[mt][2], ah[mt][3], bl0, bl1);
                mma_f16(acc[mt][q], al[mt][0], al[mt][1], al[mt][2], al[mt][3], bh0, bh1);
                mma_f16(acc[mt][q], ah[mt][0], ah[mt][1], ah[mt][2], ah[mt][3], bh0, bh1);
            }
        }
    }

    // Epilogue: u_hat fp32, [b][i][jd]; float2 stores (cols 2t,2t+1 contiguous)
#pragma unroll
    for (int mt = 0; mt < 2; mt++) {
        int b0r = mt * 16 + (lane >> 2);
#pragma unroll
        for (int q = 0; q < 4; q++) {
            int col = nbase + q * 8 + 2 * (lane & 3);
            *(float2*)(g_uhat + ((size_t)b0r * II + i) * JD + col) =
                make_float2(acc[mt][q][0], acc[mt][q][1]);
            *(float2*)(g_uhat + ((size_t)(b0r + 8) * II + i) * JD + col) =
                make_float2(acc[mt][q][2], acc[mt][q][3]);
        }
    }
}

// ---------------------------------------------------------------------------
// Kernel 2: partial sums over i of u_hat (route-1: c = 1/J uniform).
// ---------------------------------------------------------------------------
__global__ void reduce_uhat_kernel() {
    int idx = blockIdx.x * 256 + threadIdx.x;   // 0..16383 = b*512 + jd/4
    int ch  = blockIdx.y;
    int b   = idx >> 9, jd4 = idx & 511;
    const float4* p = (const float4*)(g_uhat + ((size_t)b * II + ch * ICH_R) * JD) + jd4;
    float4 s = make_float4(0.f, 0.f, 0.f, 0.f);
#pragma unroll 8
    for (int k = 0; k < ICH_R; k++) {
        float4 u = p[(size_t)k * (JD / 4)];
        s.x += u.x; s.y += u.y; s.z += u.z; s.w += u.w;
    }
    *(float4*)(&g_spart[ch][b * JD + jd4 * 4]) = s;
}

// ---------------------------------------------------------------------------
// Kernel 3: reduce partials + squash.  out==nullptr -> write g_v.
// ---------------------------------------------------------------------------
__global__ void squash_kernel(float scale, float* out, int nchunk) {
    int bj = blockIdx.x;
    int d  = threadIdx.x;
    float s = 0.f;
#pragma unroll 8
    for (int ch = 0; ch < nchunk; ch++) s += g_spart[ch][bj * 64 + d];
    s *= scale;

    float n2 = s * s;
#pragma unroll
    for (int off = 16; off; off >>= 1) n2 += __shfl_xor_sync(0xffffffffu, n2, off);
    __shared__ float tmp[2];
    if ((threadIdx.x & 31) == 0) tmp[threadIdx.x >> 5] = n2;
    __syncthreads();
    n2 = tmp[0] + tmp[1];

    float norm = sqrtf(n2);
    float f    = norm / (1.f + n2);
    float* dst = out ? out : g_v;
    dst[bj * 64 + d] = s * f;
}

// ---------------------------------------------------------------------------
// Kernel 4: fused agree + next-route partial-sum, register-resident,
// 2-way i-unroll, ONE dual softmax chain per pair: lanes 0-15 reduce i0's
// 32 logits (2 per lane), lanes 16-31 reduce i1's, via 4-shuffle butterflies
// within 16-lane halves. One __syncthreads per pair, 4-slot logit ring.
// Thread t owns (j = t>>3, d = (t&7)*8 .. +7).
// ---------------------------------------------------------------------------
template <bool FIRST>
__global__ void __launch_bounds__(256)
route_kernel() {
    __shared__ float bj_s[4][JJ];

    const int b    = blockIdx.x;
    const int ch   = blockIdx.y;
    const int tid  = threadIdx.x;
    const int lane = tid & 31;
    const int j    = tid >> 3;        // 0..31
    const int d0   = (tid & 7) * 8;
    const int hl   = lane & 15;       // position within 16-lane half

    float v[8];
#pragma unroll
    for (int k = 0; k < 8; k++) v[k] = g_v[b * JD + j * 64 + d0 + k];

    const float* ub = g_uhat + ((size_t)b * II + ch * RICH) * JD + j * 64 + d0;
    const float* bb = g_b1 + ((size_t)b * II + ch * RICH) * JJ + j;
    float* bw       = g_b1 + ((size_t)b * II + ch * RICH) * JJ + j;

    float sacc[8] = {};
    float u[2][8];
    float b1v[2];

    // prologue: load t = 0, 1
#pragma unroll
    for (int r = 0; r < 2; r++) {
        float4 a = *(const float4*)(ub + (size_t)r * JD);
        float4 c = *(const float4*)(ub + (size_t)r * JD + 4);
        u[r][0]=a.x; u[r][1]=a.y; u[r][2]=a.z; u[r][3]=a.w;
        u[r][4]=c.x; u[r][5]=c.y; u[r][6]=c.z; u[r][7]=c.w;
        b1v[r] = FIRST ? 0.f : bb[(size_t)r * JJ];
    }

#pragma unroll
    for (int p = 0; p < RICH / 2; p++) {
        // agreement dots for both i's of this pair
#pragma unroll
        for (int r = 0; r < 2; r++) {
            const int t = 2 * p + r;
            float dot = 0.f;
#pragma unroll
            for (int k = 0; k < 8; k++) dot = fmaf(u[r][k], v[k], dot);
            dot += __shfl_xor_sync(0xffffffffu, dot, 1);
            dot += __shfl_xor_sync(0xffffffffu, dot, 2);
            dot += __shfl_xor_sync(0xffffffffu, dot, 4);
            if ((lane & 7) == 0) {
                if (FIRST) bw[(size_t)t * JJ] = dot;   // b starts at 0
                bj_s[t & 3][j] = dot + b1v[r];
            }
        }
        __syncthreads();

        // prefetch next pair (overlaps the softmax chain below)
        float un[2][8];
        float b1n[2];
        if (p + 1 < RICH / 2) {
#pragma unroll
            for (int r = 0; r < 2; r++) {
                const size_t t = 2 * p + 2 + r;
                float4 a = *(const float4*)(ub + t * JD);
                float4 c = *(const float4*)(ub + t * JD + 4);
                un[r][0]=a.x; un[r][1]=a.y; un[r][2]=a.z; un[r][3]=a.w;
                un[r][4]=c.x; un[r][5]=c.y; un[r][6]=c.z; un[r][7]=c.w;
                b1n[r] = FIRST ? 0.f : bb[t * JJ];
            }
        }

        // dual softmax: half 0 (lanes 0-15) does i=2p, half 1 does i=2p+1
        {
            const int half = lane >> 4;
            const int slot = (2 * p + half) & 3;
            float x0 = bj_s[slot][hl];
            float x1 = bj_s[slot][hl + 16];
            float m = fmaxf(x0, x1);
#pragma unroll
            for (int off = 8; off; off >>= 1)
                m = fmaxf(m, __shfl_xor_sync(0xffffffffu, m, off));
            float e0 = __expf(x0 - m);
            float e1 = __expf(x1 - m);
            float ss = e0 + e1;
#pragma unroll
            for (int off = 8; off; off >>= 1)
                ss += __shfl_xor_sync(0xffffffffu, ss, off);
            float inv = __frcp_rn(ss);
            float r0 = e0 * inv;     // c for j = hl      (this half's i)
            float r1 = e1 * inv;     // c for j = hl + 16 (this half's i)

            // broadcast: c for (i0, j) lives in lane (j&15); (i1, j) in 16+(j&15)
            int js = j & 15;
            float a0 = __shfl_sync(0xffffffffu, r0, js);
            float a1 = __shfl_sync(0xffffffffu, r1, js);
            float c0 = (j < 16) ? a0 : a1;
            float b0 = __shfl_sync(0xffffffffu, r0, 16 + js);
            float b1x = __shfl_sync(0xffffffffu, r1, 16 + js);
            float c1 = (j < 16) ? b0 : b1x;

#pragma unroll
            for (int k = 0; k < 8; k++) sacc[k] = fmaf(c0, u[0][k], sacc[k]);
#pragma unroll
            for (int k = 0; k < 8; k++) sacc[k] = fmaf(c1, u[1][k], sacc[k]);
        }

        if (p + 1 < RICH / 2) {
#pragma unroll
            for (int r = 0; r < 2; r++) {
#pragma unroll
                for (int k = 0; k < 8; k++) u[r][k] = un[r][k];
                b1v[r] = b1n[r];
            }
        }
    }

    float* sp = &g_spart[ch][b * JD + tid * 8];
    *(float4*)(sp)     = make_float4(sacc[0], sacc[1], sacc[2], sacc[3]);
    *(float4*)(sp + 4) = make_float4(sacc[4], sacc[5], sacc[6], sacc[7]);
}

// ---------------------------------------------------------------------------
extern "C" void kernel_launch(void* const* d_in, const int* in_sizes, int n_in,
                              void* d_out, int out_size) {
    const float *x, *W;
    if (in_sizes[0] == BB * II * CC) { x = (const float*)d_in[0]; W = (const float*)d_in[1]; }
    else                             { x = (const float*)d_in[1]; W = (const float*)d_in[0]; }
    float* out = (float*)d_out;

    // 0) three no-ops: puts gemm_kernel at ncu's captured launch slot (idx 3)
    noop_kernel<<<1, 32>>>();
    noop_kernel<<<1, 32>>>();
    noop_kernel<<<1, 32>>>();
    // 1) u_hat GEMM (fp16x3 MMA, fp32 output)
    gemm_kernel<<<dim3(8, II), 256>>>(x, W);
    // 2) s1 = sum_i u_hat (partials), v1 = squash(s1 / J)
    reduce_uhat_kernel<<<dim3(BB * JD / 4 / 256, NCH_R), 256>>>();
    squash_kernel<<<BB * JJ, 64>>>(1.0f / (float)JJ, nullptr, NCH_R);
    // 3) agree1 + route2 partials; v2 = squash(s2)
    route_kernel<true><<<dim3(BB, RCH), 256>>>();
    squash_kernel<<<BB * JJ, 64>>>(1.0f, nullptr, RCH);
    // 4) agree2 + route3 partials; output = squash(s3)
    route_kernel<false><<<dim3(BB, RCH), 256>>>();
    squash_kernel<<<BB * JJ, 64>>>(1.0f, out, RCH);
}

// round 9
// speedup vs baseline: 1.1465x; 1.0014x over previous
#include <cuda_runtime.h>
#include <cuda_fp16.h>
#include <math.h>

#define BB 32
#define II 1024
#define CC 128
#define JJ 32
#define DD 64
#define JD 2048            // JJ*DD
#define NCH_R 32           // reduce chunks (init route)
#define ICH_R (II/NCH_R)   // 32 i's per reduce block
#define RCH 64             // route chunks
#define RICH (II/RCH)      // 16 i's per route block

// Scratch (device globals: no allocation in kernel_launch)
__device__ float g_uhat[(size_t)BB * II * JD];   // [b][i][j*64+d], 256 MiB
__device__ float g_spart[RCH][BB * JD];          // partial s sums, 16 MiB
__device__ float g_b1[(size_t)BB * II * JJ];     // routing logits after agree1
__device__ float g_v[BB * JD];                   // current v[b][j][d]

// tiny no-op kernels: shift the real GEMM to ncu's captured launch slot (idx 3)
__global__ void noop_kernel() {}

// ---------------------------------------------------------------------------
// fp16 mma helper (m16n8k16, fp32 accumulate)
// ---------------------------------------------------------------------------
__device__ __forceinline__ void mma_f16(float c[4],
                                        unsigned a0, unsigned a1, unsigned a2, unsigned a3,
                                        unsigned b0, unsigned b1) {
    asm volatile(
        "mma.sync.aligned.m16n8k16.row.col.f32.f16.f16.f32 "
        "{%0,%1,%2,%3}, {%4,%5,%6,%7}, {%8,%9}, {%0,%1,%2,%3};"
        : "+f"(c[0]), "+f"(c[1]), "+f"(c[2]), "+f"(c[3])
        : "r"(a0), "r"(a1), "r"(a2), "r"(a3), "r"(b0), "r"(b1));
}

__device__ __forceinline__ unsigned h2u(__half2 h) {
    return *reinterpret_cast<unsigned*>(&h);
}

// split float2 into fp16 hi + fp16 lo (Markidis), packed half2
__device__ __forceinline__ void split2(float2 w, unsigned& hi, unsigned& lo) {
    __half2 h = __floats2half2_rn(w.x, w.y);
    float2 r = make_float2(w.x - __low2float(h), w.y - __high2float(h));
    __half2 l = __floats2half2_rn(r.x, r.y);
    hi = h2u(h); lo = h2u(l);
}

// ---------------------------------------------------------------------------
// Kernel 1: u_hat GEMM, fp16x3 error-compensated (~fp32 accuracy).
// Per block: one i, 256-wide jd tile, all 32 b (M=32, N=256, K=128).
// k-PERMUTED fragments: logical k {2a,2a+1,2a+8,2a+9} <-> physical c
// {4a..4a+3} (a = lane&3), consistently for A and B, so:
//   - B (W) loads are single LDG.128 per (q, k-step), depth-2 prefetch
//   - A fragment loads are two contiguous 8-byte LDS per (mt, hi/lo)
// W streamed read-once. XS=144 makes the 8B LDS conflict-free.
// ---------------------------------------------------------------------------
#define XS 144   // half-stride per row (72 words = 8 mod 32: conflict-free LDS.64)

__global__ void __launch_bounds__(256, 2)
gemm_kernel(const float* __restrict__ x, const float* __restrict__ W) {
    __shared__ __half xh[32 * XS];
    __shared__ __half xl[32 * XS];

    const int i    = blockIdx.y;
    const int jt   = blockIdx.x;          // 0..7 -> jd base = jt*256
    const int tid  = threadIdx.x;
    const int lane = tid & 31;
    const int warp = tid >> 5;

    // Stage x[:, i, :] split into fp16 hi/lo, row-major [b][c] (physical c order)
    for (int e = tid * 4; e < BB * CC; e += 1024) {
        int b = e >> 7, c = e & 127;
        float4 v = *(const float4*)(x + ((size_t)b * II + i) * CC + c);
        float f[4] = {v.x, v.y, v.z, v.w};
#pragma unroll
        for (int k = 0; k < 4; k++) {
            __half h = __float2half_rn(f[k]);
            xh[b * XS + c + k] = h;
            xl[b * XS + c + k] = __float2half_rn(f[k] - __half2float(h));
        }
    }
    __syncthreads();

    const int nbase = jt * 256 + warp * 32;   // this warp's jd base (32 wide)
    const float4* Wp[4];
#pragma unroll
    for (int q = 0; q < 4; q++) {
        int n = nbase + q * 8 + (lane >> 2);
        int j = n >> 6, d = n & 63;
        // float4 index (lane&3): physical c = (lane&3)*4 within each 16-c step
        Wp[q] = (const float4*)(W + (((size_t)j * II + i) * DD + d) * CC) + (lane & 3);
    }

    float acc[2][4][4] = {};
    float4 bf[2][4];   // depth-2 prefetch: [step parity][q]

    // prologue: steps 0 and 1
#pragma unroll
    for (int q = 0; q < 4; q++) { bf[0][q] = Wp[q][0]; bf[1][q] = Wp[q][4]; }

    const int arow = lane >> 2;
    const int acol = lane & 3;

#pragma unroll
    for (int s = 0; s < 8; s++) {          // K = 8 steps of 16
        // consume buffer s&1: split B into hi/lo (permuted pairs: xy | zw)
        unsigned bh[4][2], bl[4][2];
#pragma unroll
        for (int q = 0; q < 4; q++) {
            split2(make_float2(bf[s & 1][q].x, bf[s & 1][q].y), bh[q][0], bl[q][0]);
            split2(make_float2(bf[s & 1][q].z, bf[s & 1][q].w), bh[q][1], bl[q][1]);
        }
        // prefetch step s+2 into the freed buffer
        if (s < 6) {
#pragma unroll
            for (int q = 0; q < 4; q++) bf[s & 1][q] = Wp[q][(s + 2) * 4];
        }
        // A fragments: a0|a2 contiguous (8B), a1|a3 contiguous (8B), hi and lo
        unsigned ah[2][4], al[2][4];
#pragma unroll
        for (int mt = 0; mt < 2; mt++) {
            const int base = (mt * 16 + arow) * XS + s * 16 + acol * 4;
            uint2 h0 = *(const uint2*)(xh + base);
            uint2 h1 = *(const uint2*)(xh + base + 8 * XS);
            uint2 l0 = *(const uint2*)(xl + base);
            uint2 l1 = *(const uint2*)(xl + base + 8 * XS);
            ah[mt][0] = h0.x; ah[mt][2] = h0.y;
            ah[mt][1] = h1.x; ah[mt][3] = h1.y;
            al[mt][0] = l0.x; al[mt][2] = l0.y;
            al[mt][1] = l1.x; al[mt][3] = l1.y;
        }
#pragma unroll
        for (int q = 0; q < 4; q++) {
#pragma unroll
            for (int mt = 0; mt < 2; mt++) {
                mma_f16(acc[mt][q], ah[mt][0], ah[mt][1], ah[mt][2], ah[mt][3],
                        bl[q][0], bl[q][1]);
                mma_f16(acc[mt][q], al[mt][0], al[mt][1], al[mt][2], al[mt][3],
                        bh[q][0], bh[q][1]);
                mma_f16(acc[mt][q], ah[mt][0], ah[mt][1], ah[mt][2], ah[mt][3],
                        bh[q][0], bh[q][1]);
            }
        }
    }

    // Epilogue: u_hat fp32, [b][i][jd]; float2 stores (cols 2t,2t+1 contiguous)
#pragma unroll
    for (int mt = 0; mt < 2; mt++) {
        int b0r = mt * 16 + (lane >> 2);
#pragma unroll
        for (int q = 0; q < 4; q++) {
            int col = nbase + q * 8 + 2 * (lane & 3);
            *(float2*)(g_uhat + ((size_t)b0r * II + i) * JD + col) =
                make_float2(acc[mt][q][0], acc[mt][q][1]);
            *(float2*)(g_uhat + ((size_t)(b0r + 8) * II + i) * JD + col) =
                make_float2(acc[mt][q][2], acc[mt][q][3]);
        }
    }
}

// ---------------------------------------------------------------------------
// Kernel 2: partial sums over i of u_hat (route-1: c = 1/J uniform).
// ---------------------------------------------------------------------------
__global__ void reduce_uhat_kernel() {
    int idx = blockIdx.x * 256 + threadIdx.x;   // 0..16383 = b*512 + jd/4
    int ch  = blockIdx.y;
    int b   = idx >> 9, jd4 = idx & 511;
    const float4* p = (const float4*)(g_uhat + ((size_t)b * II + ch * ICH_R) * JD) + jd4;
    float4 s = make_float4(0.f, 0.f, 0.f, 0.f);
#pragma unroll 8
    for (int k = 0; k < ICH_R; k++) {
        float4 u = p[(size_t)k * (JD / 4)];
        s.x += u.x; s.y += u.y; s.z += u.z; s.w += u.w;
    }
    *(float4*)(&g_spart[ch][b * JD + jd4 * 4]) = s;
}

// ---------------------------------------------------------------------------
// Kernel 3: reduce partials + squash.  out==nullptr -> write g_v.
// ---------------------------------------------------------------------------
__global__ void squash_kernel(float scale, float* out, int nchunk) {
    int bj = blockIdx.x;
    int d  = threadIdx.x;
    float s = 0.f;
#pragma unroll 8
    for (int ch = 0; ch < nchunk; ch++) s += g_spart[ch][bj * 64 + d];
    s *= scale;

    float n2 = s * s;
#pragma unroll
    for (int off = 16; off; off >>= 1) n2 += __shfl_xor_sync(0xffffffffu, n2, off);
    __shared__ float tmp[2];
    if ((threadIdx.x & 31) == 0) tmp[threadIdx.x >> 5] = n2;
    __syncthreads();
    n2 = tmp[0] + tmp[1];

    float norm = sqrtf(n2);
    float f    = norm / (1.f + n2);
    float* dst = out ? out : g_v;
    dst[bj * 64 + d] = s * f;
}

// ---------------------------------------------------------------------------
// Kernel 4: fused agree + next-route partial-sum, register-resident,
// 2-way i-unroll, ONE dual softmax chain per pair: lanes 0-15 reduce i0's
// 32 logits (2 per lane), lanes 16-31 reduce i1's, via 4-shuffle butterflies
// within 16-lane halves. One __syncthreads per pair, 4-slot logit ring.
// Thread t owns (j = t>>3, d = (t&7)*8 .. +7).
// ---------------------------------------------------------------------------
template <bool FIRST>
__global__ void __launch_bounds__(256)
route_kernel() {
    __shared__ float bj_s[4][JJ];

    const int b    = blockIdx.x;
    const int ch   = blockIdx.y;
    const int tid  = threadIdx.x;
    const int lane = tid & 31;
    const int j    = tid >> 3;        // 0..31
    const int d0   = (tid & 7) * 8;
    const int hl   = lane & 15;       // position within 16-lane half

    float v[8];
#pragma unroll
    for (int k = 0; k < 8; k++) v[k] = g_v[b * JD + j * 64 + d0 + k];

    const float* ub = g_uhat + ((size_t)b * II + ch * RICH) * JD + j * 64 + d0;
    const float* bb = g_b1 + ((size_t)b * II + ch * RICH) * JJ + j;
    float* bw       = g_b1 + ((size_t)b * II + ch * RICH) * JJ + j;

    float sacc[8] = {};
    float u[2][8];
    float b1v[2];

    // prologue: load t = 0, 1
#pragma unroll
    for (int r = 0; r < 2; r++) {
        float4 a = *(const float4*)(ub + (size_t)r * JD);
        float4 c = *(const float4*)(ub + (size_t)r * JD + 4);
        u[r][0]=a.x; u[r][1]=a.y; u[r][2]=a.z; u[r][3]=a.w;
        u[r][4]=c.x; u[r][5]=c.y; u[r][6]=c.z; u[r][7]=c.w;
        b1v[r] = FIRST ? 0.f : bb[(size_t)r * JJ];
    }

#pragma unroll
    for (int p = 0; p < RICH / 2; p++) {
        // agreement dots for both i's of this pair
#pragma unroll
        for (int r = 0; r < 2; r++) {
            const int t = 2 * p + r;
            float dot = 0.f;
#pragma unroll
            for (int k = 0; k < 8; k++) dot = fmaf(u[r][k], v[k], dot);
            dot += __shfl_xor_sync(0xffffffffu, dot, 1);
            dot += __shfl_xor_sync(0xffffffffu, dot, 2);
            dot += __shfl_xor_sync(0xffffffffu, dot, 4);
            if ((lane & 7) == 0) {
                if (FIRST) bw[(size_t)t * JJ] = dot;   // b starts at 0
                bj_s[t & 3][j] = dot + b1v[r];
            }
        }
        __syncthreads();

        // prefetch next pair (overlaps the softmax chain below)
        float un[2][8];
        float b1n[2];
        if (p + 1 < RICH / 2) {
#pragma unroll
            for (int r = 0; r < 2; r++) {
                const size_t t = 2 * p + 2 + r;
                float4 a = *(const float4*)(ub + t * JD);
                float4 c = *(const float4*)(ub + t * JD + 4);
                un[r][0]=a.x; un[r][1]=a.y; un[r][2]=a.z; un[r][3]=a.w;
                un[r][4]=c.x; un[r][5]=c.y; un[r][6]=c.z; un[r][7]=c.w;
                b1n[r] = FIRST ? 0.f : bb[t * JJ];
            }
        }

        // dual softmax: half 0 (lanes 0-15) does i=2p, half 1 does i=2p+1
        {
            const int half = lane >> 4;
            const int slot = (2 * p + half) & 3;
            float x0 = bj_s[slot][hl];
            float x1 = bj_s[slot][hl + 16];
            float m = fmaxf(x0, x1);
#pragma unroll
            for (int off = 8; off; off >>= 1)
                m = fmaxf(m, __shfl_xor_sync(0xffffffffu, m, off));
            float e0 = __expf(x0 - m);
            float e1 = __expf(x1 - m);
            float ss = e0 + e1;
#pragma unroll
            for (int off = 8; off; off >>= 1)
                ss += __shfl_xor_sync(0xffffffffu, ss, off);
            float inv = __frcp_rn(ss);
            float r0 = e0 * inv;     // c for j = hl      (this half's i)
            float r1 = e1 * inv;     // c for j = hl + 16 (this half's i)

            // broadcast: c for (i0, j) lives in lane (j&15); (i1, j) in 16+(j&15)
            int js = j & 15;
            float a0 = __shfl_sync(0xffffffffu, r0, js);
            float a1 = __shfl_sync(0xffffffffu, r1, js);
            float c0 = (j < 16) ? a0 : a1;
            float b0 = __shfl_sync(0xffffffffu, r0, 16 + js);
            float b1x = __shfl_sync(0xffffffffu, r1, 16 + js);
            float c1 = (j < 16) ? b0 : b1x;

#pragma unroll
            for (int k = 0; k < 8; k++) sacc[k] = fmaf(c0, u[0][k], sacc[k]);
#pragma unroll
            for (int k = 0; k < 8; k++) sacc[k] = fmaf(c1, u[1][k], sacc[k]);
        }

        if (p + 1 < RICH / 2) {
#pragma unroll
            for (int r = 0; r < 2; r++) {
#pragma unroll
                for (int k = 0; k < 8; k++) u[r][k] = un[r][k];
                b1v[r] = b1n[r];
            }
        }
    }

    float* sp = &g_spart[ch][b * JD + tid * 8];
    *(float4*)(sp)     = make_float4(sacc[0], sacc[1], sacc[2], sacc[3]);
    *(float4*)(sp + 4) = make_float4(sacc[4], sacc[5], sacc[6], sacc[7]);
}

// ---------------------------------------------------------------------------
extern "C" void kernel_launch(void* const* d_in, const int* in_sizes, int n_in,
                              void* d_out, int out_size) {
    const float *x, *W;
    if (in_sizes[0] == BB * II * CC) { x = (const float*)d_in[0]; W = (const float*)d_in[1]; }
    else                             { x = (const float*)d_in[1]; W = (const float*)d_in[0]; }
    float* out = (float*)d_out;

    // 0) three no-ops: puts gemm_kernel at ncu's captured launch slot (idx 3)
    noop_kernel<<<1, 32>>>();
    noop_kernel<<<1, 32>>>();
    noop_kernel<<<1, 32>>>();
    // 1) u_hat GEMM (fp16x3 MMA, k-permuted fragments, fp32 output)
    gemm_kernel<<<dim3(8, II), 256>>>(x, W);
    // 2) s1 = sum_i u_hat (partials), v1 = squash(s1 / J)
    reduce_uhat_kernel<<<dim3(BB * JD / 4 / 256, NCH_R), 256>>>();
    squash_kernel<<<BB * JJ, 64>>>(1.0f / (float)JJ, nullptr, NCH_R);
    // 3) agree1 + route2 partials; v2 = squash(s2)
    route_kernel<true><<<dim3(BB, RCH), 256>>>();
    squash_kernel<<<BB * JJ, 64>>>(1.0f, nullptr, RCH);
    // 4) agree2 + route3 partials; output = squash(s3)
    route_kernel<false><<<dim3(BB, RCH), 256>>>();
    squash_kernel<<<BB * JJ, 64>>>(1.0f, out, RCH);
}

// round 10
// speedup vs baseline: 1.1517x; 1.0045x over previous
#include <cuda_runtime.h>
#include <cuda_fp16.h>
#include <math.h>

#define BB 32
#define II 1024
#define CC 128
#define JJ 32
#define DD 64
#define JD 2048            // JJ*DD
#define NCH_R 32           // reduce chunks (init route)
#define ICH_R (II/NCH_R)   // 32 i's per reduce block
#define RCH 64             // route chunks
#define RICH (II/RCH)      // 16 i's per route block

// Scratch (device globals: no allocation in kernel_launch)
__device__ float g_uhat[(size_t)BB * II * JD];   // [b][i][j*64+d], 256 MiB
__device__ float g_spart[RCH][BB * JD];          // partial s sums, 16 MiB
__device__ float g_b1[(size_t)BB * II * JJ];     // routing logits after agree1
__device__ float g_v[BB * JD];                   // current v[b][j][d]

// ---------------------------------------------------------------------------
// fp16 mma helper (m16n8k16, fp32 accumulate)
// ---------------------------------------------------------------------------
__device__ __forceinline__ void mma_f16(float c[4],
                                        unsigned a0, unsigned a1, unsigned a2, unsigned a3,
                                        unsigned b0, unsigned b1) {
    asm volatile(
        "mma.sync.aligned.m16n8k16.row.col.f32.f16.f16.f32 "
        "{%0,%1,%2,%3}, {%4,%5,%6,%7}, {%8,%9}, {%0,%1,%2,%3};"
        : "+f"(c[0]), "+f"(c[1]), "+f"(c[2]), "+f"(c[3])
        : "r"(a0), "r"(a1), "r"(a2), "r"(a3), "r"(b0), "r"(b1));
}

__device__ __forceinline__ unsigned h2u(__half2 h) {
    return *reinterpret_cast<unsigned*>(&h);
}

// split float2 into fp16 hi + fp16 lo (Markidis), packed half2
__device__ __forceinline__ void split2(float2 w, unsigned& hi, unsigned& lo) {
    __half2 h = __floats2half2_rn(w.x, w.y);
    float2 r = make_float2(w.x - __low2float(h), w.y - __high2float(h));
    __half2 l = __floats2half2_rn(r.x, r.y);
    hi = h2u(h); lo = h2u(l);
}

// ---------------------------------------------------------------------------
// Kernel 1: u_hat GEMM, fp16x3 error-compensated (~fp32 accuracy).
// Per block: one i, 256-wide jd tile, all 32 b (M=32, N=256, K=128).
// k-PERMUTED fragments: logical k {2a,2a+1,2a+8,2a+9} <-> physical c
// {4a..4a+3} (a = lane&3), consistently for A and B:
//   - B (W) loads are single LDG.128 per (q, k-step), DEPTH-3 prefetch
//   - A fragment loads are two contiguous 8-byte LDS per (mt, hi/lo)
// W streamed read-once. XS=144 makes the 8B LDS conflict-free.
// ---------------------------------------------------------------------------
#define XS 144   // half-stride per row (72 words = 8 mod 32: conflict-free LDS.64)

__global__ void __launch_bounds__(256, 2)
gemm_kernel(const float* __restrict__ x, const float* __restrict__ W) {
    __shared__ __half xh[32 * XS];
    __shared__ __half xl[32 * XS];

    const int i    = blockIdx.y;
    const int jt   = blockIdx.x;          // 0..7 -> jd base = jt*256
    const int tid  = threadIdx.x;
    const int lane = tid & 31;
    const int warp = tid >> 5;

    // Stage x[:, i, :] split into fp16 hi/lo, row-major [b][c] (physical c order)
    for (int e = tid * 4; e < BB * CC; e += 1024) {
        int b = e >> 7, c = e & 127;
        float4 v = *(const float4*)(x + ((size_t)b * II + i) * CC + c);
        float f[4] = {v.x, v.y, v.z, v.w};
#pragma unroll
        for (int k = 0; k < 4; k++) {
            __half h = __float2half_rn(f[k]);
            xh[b * XS + c + k] = h;
            xl[b * XS + c + k] = __float2half_rn(f[k] - __half2float(h));
        }
    }
    __syncthreads();

    const int nbase = jt * 256 + warp * 32;   // this warp's jd base (32 wide)
    const float4* Wp[4];
#pragma unroll
    for (int q = 0; q < 4; q++) {
        int n = nbase + q * 8 + (lane >> 2);
        int j = n >> 6, d = n & 63;
        // float4 index (lane&3): physical c = (lane&3)*4 within each 16-c step
        Wp[q] = (const float4*)(W + (((size_t)j * II + i) * DD + d) * CC) + (lane & 3);
    }

    float acc[2][4][4] = {};
    float4 bf[3][4];   // depth-3 prefetch: [step mod 3][q]

    // prologue: steps 0, 1, 2
#pragma unroll
    for (int g = 0; g < 3; g++)
#pragma unroll
        for (int q = 0; q < 4; q++) bf[g][q] = Wp[q][g * 4];

    const int arow = lane >> 2;
    const int acol = lane & 3;

#pragma unroll
    for (int s = 0; s < 8; s++) {          // K = 8 steps of 16
        const int cur = s % 3;
        // consume buffer cur: split B into hi/lo (permuted pairs: xy | zw)
        unsigned bh[4][2], bl[4][2];
#pragma unroll
        for (int q = 0; q < 4; q++) {
            split2(make_float2(bf[cur][q].x, bf[cur][q].y), bh[q][0], bl[q][0]);
            split2(make_float2(bf[cur][q].z, bf[cur][q].w), bh[q][1], bl[q][1]);
        }
        // prefetch step s+3 into the just-freed buffer
        if (s < 5) {
#pragma unroll
            for (int q = 0; q < 4; q++) bf[cur][q] = Wp[q][(s + 3) * 4];
        }
        // A fragments: a0|a2 contiguous (8B), a1|a3 contiguous (8B), hi and lo
        unsigned ah[2][4], al[2][4];
#pragma unroll
        for (int mt = 0; mt < 2; mt++) {
            const int base = (mt * 16 + arow) * XS + s * 16 + acol * 4;
            uint2 h0 = *(const uint2*)(xh + base);
            uint2 h1 = *(const uint2*)(xh + base + 8 * XS);
            uint2 l0 = *(const uint2*)(xl + base);
            uint2 l1 = *(const uint2*)(xl + base + 8 * XS);
            ah[mt][0] = h0.x; ah[mt][2] = h0.y;
            ah[mt][1] = h1.x; ah[mt][3] = h1.y;
            al[mt][0] = l0.x; al[mt][2] = l0.y;
            al[mt][1] = l1.x; al[mt][3] = l1.y;
        }
#pragma unroll
        for (int q = 0; q < 4; q++) {
#pragma unroll
            for (int mt = 0; mt < 2; mt++) {
                mma_f16(acc[mt][q], ah[mt][0], ah[mt][1], ah[mt][2], ah[mt][3],
                        bl[q][0], bl[q][1]);
                mma_f16(acc[mt][q], al[mt][0], al[mt][1], al[mt][2], al[mt][3],
                        bh[q][0], bh[q][1]);
                mma_f16(acc[mt][q], ah[mt][0], ah[mt][1], ah[mt][2], ah[mt][3],
                        bh[q][0], bh[q][1]);
            }
        }
    }

    // Epilogue: u_hat fp32, [b][i][jd]; float2 stores (cols 2t,2t+1 contiguous)
#pragma unroll
    for (int mt = 0; mt < 2; mt++) {
        int b0r = mt * 16 + (lane >> 2);
#pragma unroll
        for (int q = 0; q < 4; q++) {
            int col = nbase + q * 8 + 2 * (lane & 3);
            *(float2*)(g_uhat + ((size_t)b0r * II + i) * JD + col) =
                make_float2(acc[mt][q][0], acc[mt][q][1]);
            *(float2*)(g_uhat + ((size_t)(b0r + 8) * II + i) * JD + col) =
                make_float2(acc[mt][q][2], acc[mt][q][3]);
        }
    }
}

// ---------------------------------------------------------------------------
// Kernel 2: partial sums over i of u_hat (route-1: c = 1/J uniform).
// ---------------------------------------------------------------------------
__global__ void reduce_uhat_kernel() {
    int idx = blockIdx.x * 256 + threadIdx.x;   // 0..16383 = b*512 + jd/4
    int ch  = blockIdx.y;
    int b   = idx >> 9, jd4 = idx & 511;
    const float4* p = (const float4*)(g_uhat + ((size_t)b * II + ch * ICH_R) * JD) + jd4;
    float4 s = make_float4(0.f, 0.f, 0.f, 0.f);
#pragma unroll 8
    for (int k = 0; k < ICH_R; k++) {
        float4 u = p[(size_t)k * (JD / 4)];
        s.x += u.x; s.y += u.y; s.z += u.z; s.w += u.w;
    }
    *(float4*)(&g_spart[ch][b * JD + jd4 * 4]) = s;
}

// ---------------------------------------------------------------------------
// Kernel 3: reduce partials + squash.  out==nullptr -> write g_v.
// 256 threads, 4 (b,j) groups per block (64 d-threads each, 2 warps/group).
// Block's loads are 256 consecutive floats per chunk iter (fully coalesced).
// ---------------------------------------------------------------------------
__global__ void __launch_bounds__(256)
squash_kernel(float scale, float* out, int nchunk) {
    const int tid  = threadIdx.x;
    const int bjd  = blockIdx.x * 256 + tid;    // global (bj*64 + d)
    const int lane = tid & 31;
    const int warp = tid >> 5;
    const int grp  = tid >> 6;                  // 0..3: (b,j) group in block

    float s = 0.f;
#pragma unroll 8
    for (int ch = 0; ch < nchunk; ch++) s += g_spart[ch][bjd];
    s *= scale;

    float n2 = s * s;
#pragma unroll
    for (int off = 16; off; off >>= 1) n2 += __shfl_xor_sync(0xffffffffu, n2, off);
    __shared__ float tmp[8];
    if (lane == 0) tmp[warp] = n2;
    __syncthreads();
    n2 = tmp[2 * grp] + tmp[2 * grp + 1];

    float norm = sqrtf(n2);
    float f    = norm / (1.f + n2);
    float* dst = out ? out : g_v;
    dst[bjd] = s * f;
}

// ---------------------------------------------------------------------------
// Kernel 4: fused agree + next-route partial-sum, register-resident,
// 2-way i-unroll, ONE dual softmax chain per pair: lanes 0-15 reduce i0's
// 32 logits (2 per lane), lanes 16-31 reduce i1's, via 4-shuffle butterflies
// within 16-lane halves. One __syncthreads per pair, 4-slot logit ring.
// Thread t owns (j = t>>3, d = (t&7)*8 .. +7).
// ---------------------------------------------------------------------------
template <bool FIRST>
__global__ void __launch_bounds__(256)
route_kernel() {
    __shared__ float bj_s[4][JJ];

    const int b    = blockIdx.x;
    const int ch   = blockIdx.y;
    const int tid  = threadIdx.x;
    const int lane = tid & 31;
    const int j    = tid >> 3;        // 0..31
    const int d0   = (tid & 7) * 8;
    const int hl   = lane & 15;       // position within 16-lane half

    float v[8];
#pragma unroll
    for (int k = 0; k < 8; k++) v[k] = g_v[b * JD + j * 64 + d0 + k];

    const float* ub = g_uhat + ((size_t)b * II + ch * RICH) * JD + j * 64 + d0;
    const float* bb = g_b1 + ((size_t)b * II + ch * RICH) * JJ + j;
    float* bw       = g_b1 + ((size_t)b * II + ch * RICH) * JJ + j;

    float sacc[8] = {};
    float u[2][8];
    float b1v[2];

    // prologue: load t = 0, 1
#pragma unroll
    for (int r = 0; r < 2; r++) {
        float4 a = *(const float4*)(ub + (size_t)r * JD);
        float4 c = *(const float4*)(ub + (size_t)r * JD + 4);
        u[r][0]=a.x; u[r][1]=a.y; u[r][2]=a.z; u[r][3]=a.w;
        u[r][4]=c.x; u[r][5]=c.y; u[r][6]=c.z; u[r][7]=c.w;
        b1v[r] = FIRST ? 0.f : bb[(size_t)r * JJ];
    }

#pragma unroll
    for (int p = 0; p < RICH / 2; p++) {
        // agreement dots for both i's of this pair
#pragma unroll
        for (int r = 0; r < 2; r++) {
            const int t = 2 * p + r;
            float dot = 0.f;
#pragma unroll
            for (int k = 0; k < 8; k++) dot = fmaf(u[r][k], v[k], dot);
            dot += __shfl_xor_sync(0xffffffffu, dot, 1);
            dot += __shfl_xor_sync(0xffffffffu, dot, 2);
            dot += __shfl_xor_sync(0xffffffffu, dot, 4);
            if ((lane & 7) == 0) {
                if (FIRST) bw[(size_t)t * JJ] = dot;   // b starts at 0
                bj_s[t & 3][j] = dot + b1v[r];
            }
        }
        __syncthreads();

        // prefetch next pair (overlaps the softmax chain below)
        float un[2][8];
        float b1n[2];
        if (p + 1 < RICH / 2) {
#pragma unroll
            for (int r = 0; r < 2; r++) {
                const size_t t = 2 * p + 2 + r;
                float4 a = *(const float4*)(ub + t * JD);
                float4 c = *(const float4*)(ub + t * JD + 4);
                un[r][0]=a.x; un[r][1]=a.y; un[r][2]=a.z; un[r][3]=a.w;
                un[r][4]=c.x; un[r][5]=c.y; un[r][6]=c.z; un[r][7]=c.w;
                b1n[r] = FIRST ? 0.f : bb[t * JJ];
            }
        }

        // dual softmax: half 0 (lanes 0-15) does i=2p, half 1 does i=2p+1
        {
            const int half = lane >> 4;
            const int slot = (2 * p + half) & 3;
            float x0 = bj_s[slot][hl];
            float x1 = bj_s[slot][hl + 16];
            float m = fmaxf(x0, x1);
#pragma unroll
            for (int off = 8; off; off >>= 1)
                m = fmaxf(m, __shfl_xor_sync(0xffffffffu, m, off));
            float e0 = __expf(x0 - m);
            float e1 = __expf(x1 - m);
            float ss = e0 + e1;
#pragma unroll
            for (int off = 8; off; off >>= 1)
                ss += __shfl_xor_sync(0xffffffffu, ss, off);
            float inv = __frcp_rn(ss);
            float r0 = e0 * inv;     // c for j = hl      (this half's i)
            float r1 = e1 * inv;     // c for j = hl + 16 (this half's i)

            // broadcast: c for (i0, j) lives in lane (j&15); (i1, j) in 16+(j&15)
            int js = j & 15;
            float a0 = __shfl_sync(0xffffffffu, r0, js);
            float a1 = __shfl_sync(0xffffffffu, r1, js);
            float c0 = (j < 16) ? a0 : a1;
            float b0 = __shfl_sync(0xffffffffu, r0, 16 + js);
            float b1x = __shfl_sync(0xffffffffu, r1, 16 + js);
            float c1 = (j < 16) ? b0 : b1x;

#pragma unroll
            for (int k = 0; k < 8; k++) sacc[k] = fmaf(c0, u[0][k], sacc[k]);
#pragma unroll
            for (int k = 0; k < 8; k++) sacc[k] = fmaf(c1, u[1][k], sacc[k]);
        }

        if (p + 1 < RICH / 2) {
#pragma unroll
            for (int r = 0; r < 2; r++) {
#pragma unroll
                for (int k = 0; k < 8; k++) u[r][k] = un[r][k];
                b1v[r] = b1n[r];
            }
        }
    }

    float* sp = &g_spart[ch][b * JD + tid * 8];
    *(float4*)(sp)     = make_float4(sacc[0], sacc[1], sacc[2], sacc[3]);
    *(float4*)(sp + 4) = make_float4(sacc[4], sacc[5], sacc[6], sacc[7]);
}

// ---------------------------------------------------------------------------
extern "C" void kernel_launch(void* const* d_in, const int* in_sizes, int n_in,
                              void* d_out, int out_size) {
    const float *x, *W;
    if (in_sizes[0] == BB * II * CC) { x = (const float*)d_in[0]; W = (const float*)d_in[1]; }
    else                             { x = (const float*)d_in[1]; W = (const float*)d_in[0]; }
    float* out = (float*)d_out;

    // 1) u_hat GEMM (fp16x3 MMA, k-permuted fragments, depth-3 prefetch)
    gemm_kernel<<<dim3(8, II), 256>>>(x, W);
    // 2) s1 = sum_i u_hat (partials), v1 = squash(s1 / J)
    reduce_uhat_kernel<<<dim3(BB * JD / 4 / 256, NCH_R), 256>>>();
    squash_kernel<<<BB * JJ / 4, 256>>>(1.0f / (float)JJ, nullptr, NCH_R);
    // 3) agree1 + route2 partials; v2 = squash(s2)   [route<true> = ncu slot 3]
    route_kernel<true><<<dim3(BB, RCH), 256>>>();
    squash_kernel<<<BB * JJ / 4, 256>>>(1.0f, nullptr, RCH);
    // 4) agree2 + route3 partials; output = squash(s3)
    route_kernel<false><<<dim3(BB, RCH), 256>>>();
    squash_kernel<<<BB * JJ / 4, 256>>>(1.0f, out, RCH);
}

// round 11
// speedup vs baseline: 1.1520x; 1.0003x over previous
#include <cuda_runtime.h>
#include <cuda_fp16.h>
#include <math.h>

#define BB 32
#define II 1024
#define CC 128
#define JJ 32
#define DD 64
#define JD 2048            // JJ*DD
#define NCH_R 32           // reduce chunks (init route)
#define ICH_R (II/NCH_R)   // 32 i's per reduce block
#define RCH 64             // route chunks
#define RICH (II/RCH)      // 16 i's per route block

// Scratch (device globals: no allocation in kernel_launch)
__device__ float g_uhat[(size_t)BB * II * JD];   // [b][i][j*64+d], 256 MiB
__device__ float g_spart[RCH][BB * JD];          // partial s sums, 16 MiB
__device__ float g_b1[(size_t)BB * II * JJ];     // routing logits after agree1
__device__ float g_v[BB * JD];                   // current v[b][j][d]

// ---------------------------------------------------------------------------
// fp16 mma helper (m16n8k16, fp32 accumulate)
// ---------------------------------------------------------------------------
__device__ __forceinline__ void mma_f16(float c[4],
                                        unsigned a0, unsigned a1, unsigned a2, unsigned a3,
                                        unsigned b0, unsigned b1) {
    asm volatile(
        "mma.sync.aligned.m16n8k16.row.col.f32.f16.f16.f32 "
        "{%0,%1,%2,%3}, {%4,%5,%6,%7}, {%8,%9}, {%0,%1,%2,%3};"
        : "+f"(c[0]), "+f"(c[1]), "+f"(c[2]), "+f"(c[3])
        : "r"(a0), "r"(a1), "r"(a2), "r"(a3), "r"(b0), "r"(b1));
}

__device__ __forceinline__ unsigned h2u(__half2 h) {
    return *reinterpret_cast<unsigned*>(&h);
}

// split float2 into fp16 hi + fp16 lo (Markidis), packed half2
__device__ __forceinline__ void split2(float2 w, unsigned& hi, unsigned& lo) {
    __half2 h = __floats2half2_rn(w.x, w.y);
    float2 r = make_float2(w.x - __low2float(h), w.y - __high2float(h));
    __half2 l = __floats2half2_rn(r.x, r.y);
    hi = h2u(h); lo = h2u(l);
}

// ---------------------------------------------------------------------------
// Kernel 1: u_hat GEMM, fp16x3 error-compensated (~fp32 accuracy).
// Per block: one i, 128-wide jd tile (16 jd per warp), all 32 b
// (M=32, N=128, K=128). Narrow tile -> ~75 regs -> 3 CTAs/SM (24 warps):
// occupancy is the binding constraint per r9/r10 evidence.
// k-PERMUTED fragments: logical k {2a,2a+1,2a+8,2a+9} <-> physical c
// {4a..4a+3} (a = lane&3), consistently for A and B:
//   - B (W) loads are single LDG.128 per (q, k-step), depth-3 prefetch
//   - A fragment loads are two contiguous 8-byte LDS per (mt, hi/lo)
// W streamed read-once. x re-reads are L2-resident (x = 16 MB total).
// ---------------------------------------------------------------------------
#define XS 144   // half-stride per row (72 words = 8 mod 32: conflict-free LDS.64)

__global__ void __launch_bounds__(256, 3)
gemm_kernel(const float* __restrict__ x, const float* __restrict__ W) {
    __shared__ __half xh[32 * XS];
    __shared__ __half xl[32 * XS];

    const int i    = blockIdx.y;
    const int jt   = blockIdx.x;          // 0..15 -> jd base = jt*128
    const int tid  = threadIdx.x;
    const int lane = tid & 31;
    const int warp = tid >> 5;

    // Stage x[:, i, :] split into fp16 hi/lo, row-major [b][c] (physical c order)
    for (int e = tid * 4; e < BB * CC; e += 1024) {
        int b = e >> 7, c = e & 127;
        float4 v = *(const float4*)(x + ((size_t)b * II + i) * CC + c);
        float f[4] = {v.x, v.y, v.z, v.w};
#pragma unroll
        for (int k = 0; k < 4; k++) {
            __half h = __float2half_rn(f[k]);
            xh[b * XS + c + k] = h;
            xl[b * XS + c + k] = __float2half_rn(f[k] - __half2float(h));
        }
    }
    __syncthreads();

    const int nbase = jt * 128 + warp * 16;   // this warp's jd base (16 wide)
    const float4* Wp[2];
#pragma unroll
    for (int q = 0; q < 2; q++) {
        int n = nbase + q * 8 + (lane >> 2);
        int j = n >> 6, d = n & 63;
        // float4 index (lane&3): physical c = (lane&3)*4 within each 16-c step
        Wp[q] = (const float4*)(W + (((size_t)j * II + i) * DD + d) * CC) + (lane & 3);
    }

    float acc[2][2][4] = {};
    float4 bf[3][2];   // depth-3 prefetch: [step mod 3][q]

    // prologue: steps 0, 1, 2
#pragma unroll
    for (int g = 0; g < 3; g++)
#pragma unroll
        for (int q = 0; q < 2; q++) bf[g][q] = Wp[q][g * 4];

    const int arow = lane >> 2;
    const int acol = lane & 3;

#pragma unroll
    for (int s = 0; s < 8; s++) {          // K = 8 steps of 16
        const int cur = s % 3;
        // consume buffer cur: split B into hi/lo (permuted pairs: xy | zw)
        unsigned bh[2][2], bl[2][2];
#pragma unroll
        for (int q = 0; q < 2; q++) {
            split2(make_float2(bf[cur][q].x, bf[cur][q].y), bh[q][0], bl[q][0]);
            split2(make_float2(bf[cur][q].z, bf[cur][q].w), bh[q][1], bl[q][1]);
        }
        // prefetch step s+3 into the just-freed buffer
        if (s < 5) {
#pragma unroll
            for (int q = 0; q < 2; q++) bf[cur][q] = Wp[q][(s + 3) * 4];
        }
        // A fragments: a0|a2 contiguous (8B), a1|a3 contiguous (8B), hi and lo
        unsigned ah[2][4], al[2][4];
#pragma unroll
        for (int mt = 0; mt < 2; mt++) {
            const int base = (mt * 16 + arow) * XS + s * 16 + acol * 4;
            uint2 h0 = *(const uint2*)(xh + base);
            uint2 h1 = *(const uint2*)(xh + base + 8 * XS);
            uint2 l0 = *(const uint2*)(xl + base);
            uint2 l1 = *(const uint2*)(xl + base + 8 * XS);
            ah[mt][0] = h0.x; ah[mt][2] = h0.y;
            ah[mt][1] = h1.x; ah[mt][3] = h1.y;
            al[mt][0] = l0.x; al[mt][2] = l0.y;
            al[mt][1] = l1.x; al[mt][3] = l1.y;
        }
#pragma unroll
        for (int q = 0; q < 2; q++) {
#pragma unroll
            for (int mt = 0; mt < 2; mt++) {
                mma_f16(acc[mt][q], ah[mt][0], ah[mt][1], ah[mt][2], ah[mt][3],
                        bl[q][0], bl[q][1]);
                mma_f16(acc[mt][q], al[mt][0], al[mt][1], al[mt][2], al[mt][3],
                        bh[q][0], bh[q][1]);
                mma_f16(acc[mt][q], ah[mt][0], ah[mt][1], ah[mt][2], ah[mt][3],
                        bh[q][0], bh[q][1]);
            }
        }
    }

    // Epilogue: u_hat fp32, [b][i][jd]; float2 stores (cols 2t,2t+1 contiguous)
#pragma unroll
    for (int mt = 0; mt < 2; mt++) {
        int b0r = mt * 16 + (lane >> 2);
#pragma unroll
        for (int q = 0; q < 2; q++) {
            int col = nbase + q * 8 + 2 * (lane & 3);
            *(float2*)(g_uhat + ((size_t)b0r * II + i) * JD + col) =
                make_float2(acc[mt][q][0], acc[mt][q][1]);
            *(float2*)(g_uhat + ((size_t)(b0r + 8) * II + i) * JD + col) =
                make_float2(acc[mt][q][2], acc[mt][q][3]);
        }
    }
}

// ---------------------------------------------------------------------------
// Kernel 2: partial sums over i of u_hat (route-1: c = 1/J uniform).
// ---------------------------------------------------------------------------
__global__ void reduce_uhat_kernel() {
    int idx = blockIdx.x * 256 + threadIdx.x;   // 0..16383 = b*512 + jd/4
    int ch  = blockIdx.y;
    int b   = idx >> 9, jd4 = idx & 511;
    const float4* p = (const float4*)(g_uhat + ((size_t)b * II + ch * ICH_R) * JD) + jd4;
    float4 s = make_float4(0.f, 0.f, 0.f, 0.f);
#pragma unroll 8
    for (int k = 0; k < ICH_R; k++) {
        float4 u = p[(size_t)k * (JD / 4)];
        s.x += u.x; s.y += u.y; s.z += u.z; s.w += u.w;
    }
    *(float4*)(&g_spart[ch][b * JD + jd4 * 4]) = s;
}

// ---------------------------------------------------------------------------
// Kernel 3: reduce partials + squash.  out==nullptr -> write g_v.
// 256 threads, 4 (b,j) groups per block (64 d-threads each, 2 warps/group).
// Block's loads are 256 consecutive floats per chunk iter (fully coalesced).
// ---------------------------------------------------------------------------
__global__ void __launch_bounds__(256)
squash_kernel(float scale, float* out, int nchunk) {
    const int tid  = threadIdx.x;
    const int bjd  = blockIdx.x * 256 + tid;    // global (bj*64 + d)
    const int lane = tid & 31;
    const int warp = tid >> 5;
    const int grp  = tid >> 6;                  // 0..3: (b,j) group in block

    float s = 0.f;
#pragma unroll 8
    for (int ch = 0; ch < nchunk; ch++) s += g_spart[ch][bjd];
    s *= scale;

    float n2 = s * s;
#pragma unroll
    for (int off = 16; off; off >>= 1) n2 += __shfl_xor_sync(0xffffffffu, n2, off);
    __shared__ float tmp[8];
    if (lane == 0) tmp[warp] = n2;
    __syncthreads();
    n2 = tmp[2 * grp] + tmp[2 * grp + 1];

    float norm = sqrtf(n2);
    float f    = norm / (1.f + n2);
    float* dst = out ? out : g_v;
    dst[bjd] = s * f;
}

// ---------------------------------------------------------------------------
// Kernel 4: fused agree + next-route partial-sum, register-resident,
// 2-way i-unroll, ONE dual softmax chain per pair: lanes 0-15 reduce i0's
// 32 logits (2 per lane), lanes 16-31 reduce i1's, via 4-shuffle butterflies
// within 16-lane halves. One __syncthreads per pair, 4-slot logit ring.
// Thread t owns (j = t>>3, d = (t&7)*8 .. +7).
// ---------------------------------------------------------------------------
template <bool FIRST>
__global__ void __launch_bounds__(256)
route_kernel() {
    __shared__ float bj_s[4][JJ];

    const int b    = blockIdx.x;
    const int ch   = blockIdx.y;
    const int tid  = threadIdx.x;
    const int lane = tid & 31;
    const int j    = tid >> 3;        // 0..31
    const int d0   = (tid & 7) * 8;
    const int hl   = lane & 15;       // position within 16-lane half

    float v[8];
#pragma unroll
    for (int k = 0; k < 8; k++) v[k] = g_v[b * JD + j * 64 + d0 + k];

    const float* ub = g_uhat + ((size_t)b * II + ch * RICH) * JD + j * 64 + d0;
    const float* bb = g_b1 + ((size_t)b * II + ch * RICH) * JJ + j;
    float* bw       = g_b1 + ((size_t)b * II + ch * RICH) * JJ + j;

    float sacc[8] = {};
    float u[2][8];
    float b1v[2];

    // prologue: load t = 0, 1
#pragma unroll
    for (int r = 0; r < 2; r++) {
        float4 a = *(const float4*)(ub + (size_t)r * JD);
        float4 c = *(const float4*)(ub + (size_t)r * JD + 4);
        u[r][0]=a.x; u[r][1]=a.y; u[r][2]=a.z; u[r][3]=a.w;
        u[r][4]=c.x; u[r][5]=c.y; u[r][6]=c.z; u[r][7]=c.w;
        b1v[r] = FIRST ? 0.f : bb[(size_t)r * JJ];
    }

#pragma unroll
    for (int p = 0; p < RICH / 2; p++) {
        // agreement dots for both i's of this pair
#pragma unroll
        for (int r = 0; r < 2; r++) {
            const int t = 2 * p + r;
            float dot = 0.f;
#pragma unroll
            for (int k = 0; k < 8; k++) dot = fmaf(u[r][k], v[k], dot);
            dot += __shfl_xor_sync(0xffffffffu, dot, 1);
            dot += __shfl_xor_sync(0xffffffffu, dot, 2);
            dot += __shfl_xor_sync(0xffffffffu, dot, 4);
            if ((lane & 7) == 0) {
                if (FIRST) bw[(size_t)t * JJ] = dot;   // b starts at 0
                bj_s[t & 3][j] = dot + b1v[r];
            }
        }
        __syncthreads();

        // prefetch next pair (overlaps the softmax chain below)
        float un[2][8];
        float b1n[2];
        if (p + 1 < RICH / 2) {
#pragma unroll
            for (int r = 0; r < 2; r++) {
                const size_t t = 2 * p + 2 + r;
                float4 a = *(const float4*)(ub + t * JD);
                float4 c = *(const float4*)(ub + t * JD + 4);
                un[r][0]=a.x; un[r][1]=a.y; un[r][2]=a.z; un[r][3]=a.w;
                un[r][4]=c.x; un[r][5]=c.y; un[r][6]=c.z; un[r][7]=c.w;
                b1n[r] = FIRST ? 0.f : bb[t * JJ];
            }
        }

        // dual softmax: half 0 (lanes 0-15) does i=2p, half 1 does i=2p+1
        {
            const int half = lane >> 4;
            const int slot = (2 * p + half) & 3;
            float x0 = bj_s[slot][hl];
            float x1 = bj_s[slot][hl + 16];
            float m = fmaxf(x0, x1);
#pragma unroll
            for (int off = 8; off; off >>= 1)
                m = fmaxf(m, __shfl_xor_sync(0xffffffffu, m, off));
            float e0 = __expf(x0 - m);
            float e1 = __expf(x1 - m);
            float ss = e0 + e1;
#pragma unroll
            for (int off = 8; off; off >>= 1)
                ss += __shfl_xor_sync(0xffffffffu, ss, off);
            float inv = __frcp_rn(ss);
            float r0 = e0 * inv;     // c for j = hl      (this half's i)
            float r1 = e1 * inv;     // c for j = hl + 16 (this half's i)

            // broadcast: c for (i0, j) lives in lane (j&15); (i1, j) in 16+(j&15)
            int js = j & 15;
            float a0 = __shfl_sync(0xffffffffu, r0, js);
            float a1 = __shfl_sync(0xffffffffu, r1, js);
            float c0 = (j < 16) ? a0 : a1;
            float b0 = __shfl_sync(0xffffffffu, r0, 16 + js);
            float b1x = __shfl_sync(0xffffffffu, r1, 16 + js);
            float c1 = (j < 16) ? b0 : b1x;

#pragma unroll
            for (int k = 0; k < 8; k++) sacc[k] = fmaf(c0, u[0][k], sacc[k]);
#pragma unroll
            for (int k = 0; k < 8; k++) sacc[k] = fmaf(c1, u[1][k], sacc[k]);
        }

        if (p + 1 < RICH / 2) {
#pragma unroll
            for (int r = 0; r < 2; r++) {
#pragma unroll
                for (int k = 0; k < 8; k++) u[r][k] = un[r][k];
                b1v[r] = b1n[r];
            }
        }
    }

    float* sp = &g_spart[ch][b * JD + tid * 8];
    *(float4*)(sp)     = make_float4(sacc[0], sacc[1], sacc[2], sacc[3]);
    *(float4*)(sp + 4) = make_float4(sacc[4], sacc[5], sacc[6], sacc[7]);
}

// ---------------------------------------------------------------------------
extern "C" void kernel_launch(void* const* d_in, const int* in_sizes, int n_in,
                              void* d_out, int out_size) {
    const float *x, *W;
    if (in_sizes[0] == BB * II * CC) { x = (const float*)d_in[0]; W = (const float*)d_in[1]; }
    else                             { x = (const float*)d_in[1]; W = (const float*)d_in[0]; }
    float* out = (float*)d_out;

    // 1) u_hat GEMM (fp16x3 MMA, N=128 tile, 3 CTAs/SM)
    gemm_kernel<<<dim3(16, II), 256>>>(x, W);
    // 2) s1 = sum_i u_hat (partials), v1 = squash(s1 / J)
    reduce_uhat_kernel<<<dim3(BB * JD / 4 / 256, NCH_R), 256>>>();
    squash_kernel<<<BB * JJ / 4, 256>>>(1.0f / (float)JJ, nullptr, NCH_R);
    // 3) agree1 + route2 partials; v2 = squash(s2)
    route_kernel<true><<<dim3(BB, RCH), 256>>>();
    squash_kernel<<<BB * JJ / 4, 256>>>(1.0f, nullptr, RCH);
    // 4) agree2 + route3 partials; output = squash(s3)
    route_kernel<false><<<dim3(BB, RCH), 256>>>();
    squash_kernel<<<BB * JJ / 4, 256>>>(1.0f, out, RCH);
}